// round 14
// baseline (speedup 1.0000x reference)
#include <cuda_runtime.h>
#include <cuda_fp16.h>
#include <cstdint>
#include <utility>

#define NTOK 2048
#define IFEAT 256
#define OFEAT 256
#define MDIM 8192            // GEMM M = NTOK*4
#define NC   1024            // complex GEMM N
#define KC   1024            // complex GEMM K

#define BM 128
#define BN 128
#define BK 64                // 64 halfs = 128 B per smem row
#define STAGES 3
#define NIT (KC / BK)        // 16
#define STAGE_BYTES 32768    // A 16KB + B 16KB
#define PIPE_BYTES (STAGES * STAGE_BYTES)   // 98304
#define FLAG_OFF PIPE_BYTES
#define SMEM_TOTAL (PIPE_BYTES + 128)       // 98432 -> 2 CTAs/SM
#define SROW 132             // stash row stride (floats); stash overlays dead pipeline

#define NTILES 1536          // 64 mtiles * 8 ntiles * 3 products
#define NCTAS  296           // 2 per SM, persistent

#define A_CHUNK ((size_t)MDIM * KC)   // halfs
#define B_CHUNK ((size_t)NC * KC)
#define P_CHUNK ((size_t)MDIM * NC)

// ---- scratch ----
__device__ __half g_A[3 * A_CHUNK];   // 48 MB: Xre, Xim, Xre+Xim  (fp16)
__device__ __half g_B[3 * B_CHUNK];   // 6 MB:  Wre, Wim, Wre+Wim
__device__ __half g_P[3 * P_CHUNK];   // 48 MB: P1, P2, P3 (fp16 partials)
__device__ unsigned g_cnt[512];       // per-tile arrival counters (self-resetting)
__device__ unsigned g_rdy[512];       // per-tile store-complete counters (self-resetting)
__device__ unsigned g_next;           // work-steal counter (reset by fwd_prep each launch)

// ================= compile-time Cl(4,1) -> M4(C) representation =================
struct Rho { int col[32][4]; int code[32][4]; int s[32]; };

constexpr Rho make_rho() {
    Rho R{};
    int gc[5][4] = {}; int gv[5][4] = {};
    for (int r = 0; r < 4; r++) {
        int a = r >> 1, b = r & 1;
        gc[0][r] = r ^ 2; gv[0][r] = b ? 2 : 0;                              // s1 (x) E
        gc[1][r] = r ^ 2; gv[1][r] = ((a ? 1 : 3) + (b ? 2 : 0)) & 3;        // s2 (x) E
        gc[2][r] = r;     gv[2][r] = ((a ? 2 : 0) + (b ? 2 : 0)) & 3;        // s3 (x) E
        gc[3][r] = r ^ 1; gv[3][r] = 0;                                      // I (x) sx
        gc[4][r] = r ^ 1; gv[4][r] = b ? 2 : 0;                              // I (x) J
    }
    for (int A = 0; A < 32; A++) {
        int pc[4] = {0, 1, 2, 3}, pv[4] = {0, 0, 0, 0};
        for (int i = 0; i < 5; i++)
            if ((A >> i) & 1)
                for (int r = 0; r < 4; r++) {
                    int t = pc[r];
                    pc[r] = gc[i][t];
                    pv[r] = (pv[r] + gv[i][t]) & 3;
                }
        for (int r = 0; r < 4; r++) { R.col[A][r] = pc[r]; R.code[A][r] = pv[r]; }
        int sq = (pv[0] + pv[pc[0]]) & 3;
        R.s[A] = (sq == 0) ? 1 : -1;
    }
    return R;
}
constexpr Rho RHO = make_rho();

// ---- template-unrolled transforms ----
template<int A, int R>
__device__ __forceinline__ void fx1(const float* v, float (&Lre)[4][4], float (&Lim)[4][4]) {
    constexpr int c = RHO.col[A][R];
    constexpr int k = RHO.code[A][R];
    if constexpr (k == 0) Lre[c][R] += v[A];
    else if constexpr (k == 1) Lim[c][R] += v[A];
    else if constexpr (k == 2) Lre[c][R] -= v[A];
    else                       Lim[c][R] -= v[A];
}
template<int A>
__device__ __forceinline__ void fxA(const float* v, float (&Lre)[4][4], float (&Lim)[4][4]) {
    fx1<A,0>(v,Lre,Lim); fx1<A,1>(v,Lre,Lim); fx1<A,2>(v,Lre,Lim); fx1<A,3>(v,Lre,Lim);
}
template<int... As>
__device__ __forceinline__ void fxall(const float* v, float (&Lre)[4][4], float (&Lim)[4][4],
                                      std::integer_sequence<int, As...>) {
    (fxA<As>(v, Lre, Lim), ...);
}
template<int A, int R>
__device__ __forceinline__ void fw1(const float* v, float (&Wre)[4][4], float (&Wim)[4][4]) {
    constexpr int c = RHO.col[A][R];
    constexpr int k = RHO.code[A][R];
    if constexpr (k == 0) Wre[R][c] += v[A];
    else if constexpr (k == 1) Wim[R][c] += v[A];
    else if constexpr (k == 2) Wre[R][c] -= v[A];
    else                       Wim[R][c] -= v[A];
}
template<int A>
__device__ __forceinline__ void fwA(const float* v, float (&Wre)[4][4], float (&Wim)[4][4]) {
    fw1<A,0>(v,Wre,Wim); fw1<A,1>(v,Wre,Wim); fw1<A,2>(v,Wre,Wim); fw1<A,3>(v,Wre,Wim);
}
template<int... As>
__device__ __forceinline__ void fwall(const float* v, float (&Wre)[4][4], float (&Wim)[4][4],
                                      std::integer_sequence<int, As...>) {
    (fwA<As>(v, Wre, Wim), ...);
}
template<int A, int R>
__device__ __forceinline__ float iv1(const float (&Mre)[4][4], const float (&Mim)[4][4]) {
    constexpr int t = RHO.col[A][R];
    constexpr int k = RHO.code[A][R];
    if constexpr (k == 0) return  Mre[t][R];
    else if constexpr (k == 1) return -Mim[t][R];
    else if constexpr (k == 2) return -Mre[t][R];
    else                       return  Mim[t][R];
}
template<int A>
__device__ __forceinline__ float bladeA(const float (&Mre)[4][4], const float (&Mim)[4][4]) {
    constexpr float s = 0.25f * (float)RHO.s[A];
    return s * (iv1<A,0>(Mre,Mim) + iv1<A,1>(Mre,Mim) + iv1<A,2>(Mre,Mim) + iv1<A,3>(Mre,Mim));
}
template<int... As>
__device__ __forceinline__ void blades(float* v, const float (&Mre)[4][4], const float (&Mim)[4][4],
                                       std::integer_sequence<int, As...>) {
    ((v[As] = bladeA<As>(Mre, Mim)), ...);
}

// ================= PTX helpers =================
__device__ __forceinline__ uint32_t smem_u32(const void* p) {
    uint32_t a;
    asm("{ .reg .u64 t; cvta.to.shared.u64 t, %1; cvt.u32.u64 %0, t; }" : "=r"(a) : "l"(p));
    return a;
}
__device__ __forceinline__ void cp16(uint32_t s, const void* g) {
    asm volatile("cp.async.cg.shared.global [%0], [%1], 16;" :: "r"(s), "l"(g) : "memory");
}
__device__ __forceinline__ void ldsm4(uint32_t* r, uint32_t a) {
    asm volatile("ldmatrix.sync.aligned.m8n8.x4.shared.b16 {%0,%1,%2,%3}, [%4];"
        : "=r"(r[0]), "=r"(r[1]), "=r"(r[2]), "=r"(r[3]) : "r"(a));
}
__device__ __forceinline__ void mma16(float* d, const uint32_t* a, uint32_t b0, uint32_t b1) {
    asm volatile("mma.sync.aligned.m16n8k16.row.col.f32.f16.f16.f32 "
        "{%0,%1,%2,%3}, {%4,%5,%6,%7}, {%8,%9}, {%0,%1,%2,%3};"
        : "+f"(d[0]), "+f"(d[1]), "+f"(d[2]), "+f"(d[3])
        : "r"(a[0]), "r"(a[1]), "r"(a[2]), "r"(a[3]), "r"(b0), "r"(b1));
}
__device__ __forceinline__ uint2 h4(float a, float b, float c, float d) {
    __half2 lo = __floats2half2_rn(a, b);
    __half2 hi = __floats2half2_rn(c, d);
    uint2 r;
    r.x = *reinterpret_cast<uint32_t*>(&lo);
    r.y = *reinterpret_cast<uint32_t*>(&hi);
    return r;
}
__device__ __forceinline__ uint4 h8(float a, float b, float c, float d,
                                    float e, float f, float g, float h) {
    __half2 p0 = __floats2half2_rn(a, b);
    __half2 p1 = __floats2half2_rn(c, d);
    __half2 p2 = __floats2half2_rn(e, f);
    __half2 p3 = __floats2half2_rn(g, h);
    uint4 r;
    r.x = *reinterpret_cast<uint32_t*>(&p0);
    r.y = *reinterpret_cast<uint32_t*>(&p1);
    r.z = *reinterpret_cast<uint32_t*>(&p2);
    r.w = *reinterpret_cast<uint32_t*>(&p3);
    return r;
}
__device__ __forceinline__ float rt16(float v) {           // fp16 round-trip
    return __half2float(__float2half_rn(v));
}
__device__ __forceinline__ float4 ld4h(const __half* p) {
    uint2 u = *reinterpret_cast<const uint2*>(p);
    __half2 h0 = *reinterpret_cast<__half2*>(&u.x);
    __half2 h1 = *reinterpret_cast<__half2*>(&u.y);
    float2 f0 = __half22float2(h0), f1 = __half22float2(h1);
    return make_float4(f0.x, f0.y, f1.x, f1.y);
}

// ================= merged prep kernel =================
// blocks [0, 256): w transform ; blocks [256, 1280): x transform (2 features/thread)
// block 0 thread 0 also resets the work-steal counter (stream-ordered before GEMM).
#define WBLOCKS 256
__global__ __launch_bounds__(256) void fwd_prep(const float* __restrict__ x,
                                                const float* __restrict__ w) {
    if (blockIdx.x < WBLOCKS) {
        if (blockIdx.x == 0 && threadIdx.x == 0) g_next = 0u;
        int idx = blockIdx.x * 256 + threadIdx.x;     // 0 .. 65535 (o,i), i fastest
        float v[32];
        const float4* wv = reinterpret_cast<const float4*>(w) + (size_t)idx * 8;
        #pragma unroll
        for (int q = 0; q < 8; q++) {
            float4 t = wv[q];
            v[4*q] = t.x; v[4*q+1] = t.y; v[4*q+2] = t.z; v[4*q+3] = t.w;
        }
        float Wre[4][4] = {}, Wim[4][4] = {};
        fwall(v, Wre, Wim, std::make_integer_sequence<int, 32>{});
        int o = idx >> 8, i = idx & 255;
        #pragma unroll
        for (int t = 0; t < 4; t++) {
            size_t base = (size_t)(o * 4 + t) * KC + i * 4;
            *reinterpret_cast<uint2*>(g_B + base) =
                h4(Wre[t][0], Wre[t][1], Wre[t][2], Wre[t][3]);
            *reinterpret_cast<uint2*>(g_B + B_CHUNK + base) =
                h4(Wim[t][0], Wim[t][1], Wim[t][2], Wim[t][3]);
            *reinterpret_cast<uint2*>(g_B + 2 * B_CHUNK + base) =
                h4(Wre[t][0] + Wim[t][0], Wre[t][1] + Wim[t][1],
                   Wre[t][2] + Wim[t][2], Wre[t][3] + Wim[t][3]);
        }
        return;
    }
    int idx = (blockIdx.x - WBLOCKS) * 256 + threadIdx.x;   // over NTOK * IFEAT/2
    int n  = idx >> 7;
    int i0 = (idx & 127) * 2;
    float v0[32], v1[32];
    const float4* xv = reinterpret_cast<const float4*>(x) + ((size_t)n * 256 + i0) * 8;
    #pragma unroll
    for (int q = 0; q < 8; q++) {
        float4 t = xv[q];
        v0[4*q] = t.x; v0[4*q+1] = t.y; v0[4*q+2] = t.z; v0[4*q+3] = t.w;
    }
    #pragma unroll
    for (int q = 0; q < 8; q++) {
        float4 t = xv[8 + q];
        v1[4*q] = t.x; v1[4*q+1] = t.y; v1[4*q+2] = t.z; v1[4*q+3] = t.w;
    }
    float Lre0[4][4] = {}, Lim0[4][4] = {}, Lre1[4][4] = {}, Lim1[4][4] = {};
    fxall(v0, Lre0, Lim0, std::make_integer_sequence<int, 32>{});
    fxall(v1, Lre1, Lim1, std::make_integer_sequence<int, 32>{});
    #pragma unroll
    for (int c = 0; c < 4; c++) {
        size_t base = (size_t)(n * 4 + c) * KC + i0 * 4;
        *reinterpret_cast<uint4*>(g_A + base) =
            h8(Lre0[c][0], Lre0[c][1], Lre0[c][2], Lre0[c][3],
               Lre1[c][0], Lre1[c][1], Lre1[c][2], Lre1[c][3]);
        *reinterpret_cast<uint4*>(g_A + A_CHUNK + base) =
            h8(Lim0[c][0], Lim0[c][1], Lim0[c][2], Lim0[c][3],
               Lim1[c][0], Lim1[c][1], Lim1[c][2], Lim1[c][3]);
        *reinterpret_cast<uint4*>(g_A + 2 * A_CHUNK + base) =
            h8(Lre0[c][0] + Lim0[c][0], Lre0[c][1] + Lim0[c][1],
               Lre0[c][2] + Lim0[c][2], Lre0[c][3] + Lim0[c][3],
               Lre1[c][0] + Lim1[c][0], Lre1[c][1] + Lim1[c][1],
               Lre1[c][2] + Lim1[c][2], Lre1[c][3] + Lim1[c][3]);
    }
}

// ================= persistent GEMM + last-sibling fused epilogue =================
__device__ __forceinline__ void load_stage(uint32_t sm, const __half* gA, const __half* gB,
                                           int it, int tid) {
    const int k0 = it * BK;
    #pragma unroll
    for (int r = 0; r < 8; r++) {
        int slot = tid + r * 128;          // 0..1023
        int row  = slot >> 3;              // 0..127
        int c    = slot & 7;               // 16B chunk within 128B row
        uint32_t sw = (uint32_t)(row * 128 + ((c ^ (row & 7)) << 4));
        cp16(sm + sw,         gA + (size_t)row * KC + k0 + c * 8);
        cp16(sm + 16384 + sw, gB + (size_t)row * KC + k0 + c * 8);
    }
}

__global__ __launch_bounds__(128, 2)
void versor_mma(float* __restrict__ out) {
    extern __shared__ char smem[];
    const uint32_t sbase = smem_u32(smem);
    const int tid  = threadIdx.x;
    const int wid  = tid >> 5;
    const int lane = tid & 31;
    const int wm   = wid & 1;
    const int wn   = wid >> 1;

    const int lx  = lane & 7;
    const int akb = (lane >> 4) & 1;
    const int bkb = (lane >> 3) & 1;
    const uint32_t aRow = (uint32_t)((wm * 64 + lx + ((lane >> 3) & 1) * 8) * 128);
    const uint32_t bRow = 16384u + (uint32_t)((wn * 64 + lx + ((lane >> 4) & 1) * 8) * 128);
    const int qc   = lane & 3;
    const int rofs = lane >> 2;

    volatile unsigned* sctl = reinterpret_cast<volatile unsigned*>(smem + FLAG_OFF);
    // sctl[0] = last-flag, sctl[1] = tile index

    for (;;) {
        // grab next tile (broadcast via smem)
        if (tid == 0) sctl[1] = atomicAdd(&g_next, 1u);
        __syncthreads();
        const int t = (int)sctl[1];
        if (t >= NTILES) break;

        const int z     = t % 3;
        const int ntile = (t / 3) & 7;
        const int mtile = t / 24;
        const int M0 = mtile * BM;
        const int N0 = ntile * BN;
        const int tileid = mtile * 8 + ntile;

        const __half* gA = g_A + (size_t)z * A_CHUNK + (size_t)M0 * KC;
        const __half* gB = g_B + (size_t)z * B_CHUNK + (size_t)N0 * KC;
        __half* gP = g_P + (size_t)z * P_CHUNK;

        float acc[4][8][4];
        #pragma unroll
        for (int mi = 0; mi < 4; mi++)
            #pragma unroll
            for (int nj = 0; nj < 8; nj++)
                #pragma unroll
                for (int q = 0; q < 4; q++) acc[mi][nj][q] = 0.0f;

        load_stage(sbase, gA, gB, 0, tid);
        asm volatile("cp.async.commit_group;" ::: "memory");
        load_stage(sbase + STAGE_BYTES, gA, gB, 1, tid);
        asm volatile("cp.async.commit_group;" ::: "memory");

        uint32_t a[2][4][4], b[2][4][4];   // double-buffered fragments

        #pragma unroll 1
        for (int it = 0; it < NIT; it++) {
            asm volatile("cp.async.wait_group 1;" ::: "memory");
            __syncthreads();
            int nx = it + STAGES - 1;
            if (nx < NIT)
                load_stage(sbase + (uint32_t)(nx % STAGES) * STAGE_BYTES, gA, gB, nx, tid);
            asm volatile("cp.async.commit_group;" ::: "memory");

            const uint32_t sm = sbase + (uint32_t)(it % STAGES) * STAGE_BYTES;
            {
                const uint32_t cA = (uint32_t)((akb ^ lx) << 4);
                const uint32_t cB = (uint32_t)((bkb ^ lx) << 4);
                #pragma unroll
                for (int mi = 0; mi < 4; mi++)
                    ldsm4(a[0][mi], sm + aRow + (uint32_t)(mi * 2048) + cA);
                #pragma unroll
                for (int nj2 = 0; nj2 < 4; nj2++)
                    ldsm4(b[0][nj2], sm + bRow + (uint32_t)(nj2 * 2048) + cB);
            }
            #pragma unroll
            for (int ks = 0; ks < 4; ks++) {
                const int cur = ks & 1, nxt = cur ^ 1;
                if (ks < 3) {
                    const uint32_t cA = (uint32_t)((((ks + 1) * 2 + akb) ^ lx) << 4);
                    const uint32_t cB = (uint32_t)((((ks + 1) * 2 + bkb) ^ lx) << 4);
                    #pragma unroll
                    for (int mi = 0; mi < 4; mi++)
                        ldsm4(a[nxt][mi], sm + aRow + (uint32_t)(mi * 2048) + cA);
                    #pragma unroll
                    for (int nj2 = 0; nj2 < 4; nj2++)
                        ldsm4(b[nxt][nj2], sm + bRow + (uint32_t)(nj2 * 2048) + cB);
                }
                #pragma unroll
                for (int mi = 0; mi < 4; mi++)
                    #pragma unroll
                    for (int nj2 = 0; nj2 < 4; nj2++) {
                        mma16(acc[mi][2 * nj2],     a[cur][mi], b[cur][nj2][0], b[cur][nj2][1]);
                        mma16(acc[mi][2 * nj2 + 1], a[cur][mi], b[cur][nj2][2], b[cur][nj2][3]);
                    }
            }
        }
        asm volatile("cp.async.wait_group 0;" ::: "memory");
        __syncthreads();

        // ---- arrival-first protocol ----
        if (tid == 0) {
            unsigned r = atomicAdd(&g_cnt[tileid], 1u);
            unsigned last = (r == 2u);
            if (last) g_cnt[tileid] = 0u;    // self-reset for next graph replay
            sctl[0] = last;
        }
        __syncthreads();

        if (sctl[0] == 0u) {
            // not last: store my product tile as fp16, signal ready
            #pragma unroll
            for (int mi = 0; mi < 4; mi++) {
                const int row0 = M0 + wm * 64 + mi * 16 + rofs;
                #pragma unroll
                for (int nj = 0; nj < 8; nj++) {
                    const int col = N0 + wn * 64 + nj * 8 + 2 * qc;
                    *reinterpret_cast<__half2*>(gP + (size_t)row0 * NC + col) =
                        __floats2half2_rn(acc[mi][nj][0], acc[mi][nj][1]);
                    *reinterpret_cast<__half2*>(gP + (size_t)(row0 + 8) * NC + col) =
                        __floats2half2_rn(acc[mi][nj][2], acc[mi][nj][3]);
                }
            }
            __threadfence();                 // publish P stores before ready increment
            __syncthreads();
            if (tid == 0) atomicAdd(&g_rdy[tileid], 1u);
            continue;                        // grab next tile
        }

        // ---- last sibling: combine + blades + normalize ----
        float* S = reinterpret_cast<float*>(smem);   // overlays dead pipeline
        #pragma unroll
        for (int mi = 0; mi < 4; mi++) {
            const int rl = wm * 64 + mi * 16 + rofs;
            #pragma unroll
            for (int nj = 0; nj < 8; nj++) {
                const int cl = wn * 64 + nj * 8 + 2 * qc;
                *reinterpret_cast<float2*>(&S[rl * SROW + cl]) =
                    make_float2(rt16(acc[mi][nj][0]), rt16(acc[mi][nj][1]));
                *reinterpret_cast<float2*>(&S[(rl + 8) * SROW + cl]) =
                    make_float2(rt16(acc[mi][nj][2]), rt16(acc[mi][nj][3]));
            }
        }
        if (tid == 0) {
            while (atomicAdd(&g_rdy[tileid], 0u) < 2u) { }   // siblings' stores
            g_rdy[tileid] = 0u;              // self-reset for next graph replay
            __threadfence();                 // acquire
        }
        __syncthreads();

        const int za = (z + 1) % 3, zb = (z + 2) % 3;
        const __half* Pa = g_P + (size_t)za * P_CHUNK;
        const __half* Pb = g_P + (size_t)zb * P_CHUNK;

        #pragma unroll 1
        for (int e = 0; e < 8; e++) {
            const int cell = tid + e * 128;      // 0..1023
            const int tt = cell >> 5;            // token within tile 0..31
            const int g = cell & 31;             // o-group 0..31
            float Mre[4][4], Mim[4][4];
            #pragma unroll
            for (int c = 0; c < 4; c++) {
                const size_t goff = (size_t)(M0 + 4 * tt + c) * NC + N0 + 4 * g;
                float4 vo = *reinterpret_cast<const float4*>(&S[(4 * tt + c) * SROW + 4 * g]);
                float4 va = ld4h(Pa + goff);
                float4 vb = ld4h(Pb + goff);
                float4 p1, p2, p3;
                if (z == 0)      { p1 = vo; p2 = va; p3 = vb; }
                else if (z == 1) { p1 = vb; p2 = vo; p3 = va; }
                else             { p1 = va; p2 = vb; p3 = vo; }
                Mre[0][c] = p1.x - p2.x; Mim[0][c] = p3.x - p1.x - p2.x;
                Mre[1][c] = p1.y - p2.y; Mim[1][c] = p3.y - p1.y - p2.y;
                Mre[2][c] = p1.z - p2.z; Mim[2][c] = p3.z - p1.z - p2.z;
                Mre[3][c] = p1.w - p2.w; Mim[3][c] = p3.w - p1.w - p2.w;
            }
            float v[32];
            blades(v, Mre, Mim, std::make_integer_sequence<int, 32>{});
            float ss = 1e-6f;
            #pragma unroll
            for (int k = 0; k < 32; k++) ss += v[k] * v[k];
            const float inv = rsqrtf(ss);

            const int n_global = (M0 >> 2) + tt;
            const int o_global = (N0 >> 2) + g;
            float4* dst = reinterpret_cast<float4*>(out + ((size_t)n_global * 256 + o_global) * 32);
            #pragma unroll
            for (int q = 0; q < 8; q++)
                dst[q] = make_float4(v[4*q] * inv, v[4*q+1] * inv, v[4*q+2] * inv, v[4*q+3] * inv);
        }
        // loop back: grab-sync at loop top orders S reads before next load_stage writes
    }
}

// ================= host =================
extern "C" void kernel_launch(void* const* d_in, const int* in_sizes, int n_in,
                              void* d_out, int out_size) {
    const float* x = (const float*)d_in[0];   // [2048, 256, 32]
    const float* w = (const float*)d_in[1];   // [256, 256, 32]
    float* out = (float*)d_out;               // [2048, 256, 32]

    fwd_prep<<<WBLOCKS + (NTOK * IFEAT / 2) / 256, 256>>>(x, w);

    cudaFuncSetAttribute(versor_mma, cudaFuncAttributeMaxDynamicSharedMemorySize, SMEM_TOTAL);
    versor_mma<<<NCTAS, 128, SMEM_TOTAL>>>(out);
}

// round 16
// speedup vs baseline: 1.0381x; 1.0381x over previous
#include <cuda_runtime.h>
#include <cuda_fp16.h>
#include <cstdint>
#include <utility>

#define NTOK 2048
#define IFEAT 256
#define OFEAT 256
#define MDIM 8192            // GEMM M = NTOK*4
#define NC   1024            // complex GEMM N
#define KC   1024            // complex GEMM K

#define BM 128
#define BN 128
#define BK 64                // 64 halfs = 128 B per smem row
#define STAGES 3
#define NIT (KC / BK)        // 16
#define STAGE_BYTES 32768    // A 16KB + B 16KB
#define PIPE_BYTES (STAGES * STAGE_BYTES)   // 98304
#define FLAG_OFF PIPE_BYTES
#define SMEM_TOTAL (PIPE_BYTES + 128)       // 98432 -> 2 CTAs/SM
#define SROW 132             // stash row stride (floats); stash overlays dead pipeline

#define A_CHUNK ((size_t)MDIM * KC)   // halfs
#define B_CHUNK ((size_t)NC * KC)
#define P_CHUNK ((size_t)MDIM * NC)

// ---- scratch ----
__device__ __half g_A[3 * A_CHUNK];   // 48 MB: Xre, Xim, Xre+Xim  (fp16)
__device__ __half g_B[3 * B_CHUNK];   // 6 MB:  Wre, Wim, Wre+Wim
__device__ __half g_P[3 * P_CHUNK];   // 48 MB: P1, P2, P3 (fp16 partials)
__device__ unsigned g_cnt[512];       // per-tile arrival counters (self-resetting)
__device__ unsigned g_rdy[512];       // per-tile store-complete counters (self-resetting)

// ================= compile-time Cl(4,1) -> M4(C) representation =================
struct Rho { int col[32][4]; int code[32][4]; int s[32]; };

constexpr Rho make_rho() {
    Rho R{};
    int gc[5][4] = {}; int gv[5][4] = {};
    for (int r = 0; r < 4; r++) {
        int a = r >> 1, b = r & 1;
        gc[0][r] = r ^ 2; gv[0][r] = b ? 2 : 0;                              // s1 (x) E
        gc[1][r] = r ^ 2; gv[1][r] = ((a ? 1 : 3) + (b ? 2 : 0)) & 3;        // s2 (x) E
        gc[2][r] = r;     gv[2][r] = ((a ? 2 : 0) + (b ? 2 : 0)) & 3;        // s3 (x) E
        gc[3][r] = r ^ 1; gv[3][r] = 0;                                      // I (x) sx
        gc[4][r] = r ^ 1; gv[4][r] = b ? 2 : 0;                              // I (x) J
    }
    for (int A = 0; A < 32; A++) {
        int pc[4] = {0, 1, 2, 3}, pv[4] = {0, 0, 0, 0};
        for (int i = 0; i < 5; i++)
            if ((A >> i) & 1)
                for (int r = 0; r < 4; r++) {
                    int t = pc[r];
                    pc[r] = gc[i][t];
                    pv[r] = (pv[r] + gv[i][t]) & 3;
                }
        for (int r = 0; r < 4; r++) { R.col[A][r] = pc[r]; R.code[A][r] = pv[r]; }
        int sq = (pv[0] + pv[pc[0]]) & 3;
        R.s[A] = (sq == 0) ? 1 : -1;
    }
    return R;
}
constexpr Rho RHO = make_rho();

// ---- template-unrolled transforms ----
template<int A, int R>
__device__ __forceinline__ void fx1(const float* v, float (&Lre)[4][4], float (&Lim)[4][4]) {
    constexpr int c = RHO.col[A][R];
    constexpr int k = RHO.code[A][R];
    if constexpr (k == 0) Lre[c][R] += v[A];
    else if constexpr (k == 1) Lim[c][R] += v[A];
    else if constexpr (k == 2) Lre[c][R] -= v[A];
    else                       Lim[c][R] -= v[A];
}
template<int A>
__device__ __forceinline__ void fxA(const float* v, float (&Lre)[4][4], float (&Lim)[4][4]) {
    fx1<A,0>(v,Lre,Lim); fx1<A,1>(v,Lre,Lim); fx1<A,2>(v,Lre,Lim); fx1<A,3>(v,Lre,Lim);
}
template<int... As>
__device__ __forceinline__ void fxall(const float* v, float (&Lre)[4][4], float (&Lim)[4][4],
                                      std::integer_sequence<int, As...>) {
    (fxA<As>(v, Lre, Lim), ...);
}
template<int A, int R>
__device__ __forceinline__ void fw1(const float* v, float (&Wre)[4][4], float (&Wim)[4][4]) {
    constexpr int c = RHO.col[A][R];
    constexpr int k = RHO.code[A][R];
    if constexpr (k == 0) Wre[R][c] += v[A];
    else if constexpr (k == 1) Wim[R][c] += v[A];
    else if constexpr (k == 2) Wre[R][c] -= v[A];
    else                       Wim[R][c] -= v[A];
}
template<int A>
__device__ __forceinline__ void fwA(const float* v, float (&Wre)[4][4], float (&Wim)[4][4]) {
    fw1<A,0>(v,Wre,Wim); fw1<A,1>(v,Wre,Wim); fw1<A,2>(v,Wre,Wim); fw1<A,3>(v,Wre,Wim);
}
template<int... As>
__device__ __forceinline__ void fwall(const float* v, float (&Wre)[4][4], float (&Wim)[4][4],
                                      std::integer_sequence<int, As...>) {
    (fwA<As>(v, Wre, Wim), ...);
}
template<int A, int R>
__device__ __forceinline__ float iv1(const float (&Mre)[4][4], const float (&Mim)[4][4]) {
    constexpr int t = RHO.col[A][R];
    constexpr int k = RHO.code[A][R];
    if constexpr (k == 0) return  Mre[t][R];
    else if constexpr (k == 1) return -Mim[t][R];
    else if constexpr (k == 2) return -Mre[t][R];
    else                       return  Mim[t][R];
}
template<int A>
__device__ __forceinline__ float bladeA(const float (&Mre)[4][4], const float (&Mim)[4][4]) {
    constexpr float s = 0.25f * (float)RHO.s[A];
    return s * (iv1<A,0>(Mre,Mim) + iv1<A,1>(Mre,Mim) + iv1<A,2>(Mre,Mim) + iv1<A,3>(Mre,Mim));
}
template<int... As>
__device__ __forceinline__ void blades(float* v, const float (&Mre)[4][4], const float (&Mim)[4][4],
                                       std::integer_sequence<int, As...>) {
    ((v[As] = bladeA<As>(Mre, Mim)), ...);
}

// ================= PTX helpers =================
__device__ __forceinline__ uint32_t smem_u32(const void* p) {
    uint32_t a;
    asm("{ .reg .u64 t; cvta.to.shared.u64 t, %1; cvt.u32.u64 %0, t; }" : "=r"(a) : "l"(p));
    return a;
}
__device__ __forceinline__ void cp16(uint32_t s, const void* g) {
    asm volatile("cp.async.cg.shared.global [%0], [%1], 16;" :: "r"(s), "l"(g) : "memory");
}
__device__ __forceinline__ void ldsm4(uint32_t* r, uint32_t a) {
    asm volatile("ldmatrix.sync.aligned.m8n8.x4.shared.b16 {%0,%1,%2,%3}, [%4];"
        : "=r"(r[0]), "=r"(r[1]), "=r"(r[2]), "=r"(r[3]) : "r"(a));
}
__device__ __forceinline__ void mma16(float* d, const uint32_t* a, uint32_t b0, uint32_t b1) {
    asm volatile("mma.sync.aligned.m16n8k16.row.col.f32.f16.f16.f32 "
        "{%0,%1,%2,%3}, {%4,%5,%6,%7}, {%8,%9}, {%0,%1,%2,%3};"
        : "+f"(d[0]), "+f"(d[1]), "+f"(d[2]), "+f"(d[3])
        : "r"(a[0]), "r"(a[1]), "r"(a[2]), "r"(a[3]), "r"(b0), "r"(b1));
}
__device__ __forceinline__ uint2 h4(float a, float b, float c, float d) {
    __half2 lo = __floats2half2_rn(a, b);
    __half2 hi = __floats2half2_rn(c, d);
    uint2 r;
    r.x = *reinterpret_cast<uint32_t*>(&lo);
    r.y = *reinterpret_cast<uint32_t*>(&hi);
    return r;
}
__device__ __forceinline__ float rt16(float v) {           // fp16 round-trip
    return __half2float(__float2half_rn(v));
}
__device__ __forceinline__ float4 ld4h(const __half* p) {
    uint2 u = *reinterpret_cast<const uint2*>(p);
    __half2 h0 = *reinterpret_cast<__half2*>(&u.x);
    __half2 h1 = *reinterpret_cast<__half2*>(&u.y);
    float2 f0 = __half22float2(h0), f1 = __half22float2(h1);
    return make_float4(f0.x, f0.y, f1.x, f1.y);
}

// ================= merged prep kernel (smem-transpose staged) =================
// blocks [0, 256): w transform ; blocks [256, 2304): x transform
// Each block stages 256 multivectors (32 KB) through smem:
//   gmem reads fully coalesced (float4 linear); smem stride 33 floats ->
//   conflict-free reads. Writes are SCALAR (stride 33 is not float4-aligned).
#define WBLOCKS 256
__global__ __launch_bounds__(256) void fwd_prep(const float* __restrict__ x,
                                                const float* __restrict__ w) {
    __shared__ float s[256 * 33];
    const int tid = threadIdx.x;
    const bool is_w = blockIdx.x < WBLOCKS;
    const int blk = is_w ? blockIdx.x : (blockIdx.x - WBLOCKS);
    const float4* src = reinterpret_cast<const float4*>(is_w ? w : x) + (size_t)blk * 2048;

    #pragma unroll
    for (int r = 0; r < 8; r++) {
        int g = tid + r * 256;             // 0..2047 float4s, coalesced
        float4 t = src[g];
        int pair = g >> 3, j4 = g & 7;
        float* d = &s[pair * 33 + j4 * 4];
        d[0] = t.x; d[1] = t.y; d[2] = t.z; d[3] = t.w;   // scalar: alignment-safe
    }
    __syncthreads();

    float v[32];
    #pragma unroll
    for (int q = 0; q < 32; q++) v[q] = s[tid * 33 + q];   // stride 33: conflict-free

    const int idx = blk * 256 + tid;       // (n,i) or (o,i), i fastest

    if (is_w) {
        float Wre[4][4] = {}, Wim[4][4] = {};
        fwall(v, Wre, Wim, std::make_integer_sequence<int, 32>{});
        int o = idx >> 8, i = idx & 255;
        #pragma unroll
        for (int t = 0; t < 4; t++) {
            size_t base = (size_t)(o * 4 + t) * KC + i * 4;
            *reinterpret_cast<uint2*>(g_B + base) =
                h4(Wre[t][0], Wre[t][1], Wre[t][2], Wre[t][3]);
            *reinterpret_cast<uint2*>(g_B + B_CHUNK + base) =
                h4(Wim[t][0], Wim[t][1], Wim[t][2], Wim[t][3]);
            *reinterpret_cast<uint2*>(g_B + 2 * B_CHUNK + base) =
                h4(Wre[t][0] + Wim[t][0], Wre[t][1] + Wim[t][1],
                   Wre[t][2] + Wim[t][2], Wre[t][3] + Wim[t][3]);
        }
    } else {
        float Lre[4][4] = {}, Lim[4][4] = {};
        fxall(v, Lre, Lim, std::make_integer_sequence<int, 32>{});
        int n = idx >> 8, i = idx & 255;
        #pragma unroll
        for (int c = 0; c < 4; c++) {
            size_t base = (size_t)(n * 4 + c) * KC + i * 4;
            *reinterpret_cast<uint2*>(g_A + base) =
                h4(Lre[c][0], Lre[c][1], Lre[c][2], Lre[c][3]);
            *reinterpret_cast<uint2*>(g_A + A_CHUNK + base) =
                h4(Lim[c][0], Lim[c][1], Lim[c][2], Lim[c][3]);
            *reinterpret_cast<uint2*>(g_A + 2 * A_CHUNK + base) =
                h4(Lre[c][0] + Lim[c][0], Lre[c][1] + Lim[c][1],
                   Lre[c][2] + Lim[c][2], Lre[c][3] + Lim[c][3]);
        }
    }
}

// ================= GEMM + last-sibling fused epilogue =================
__device__ __forceinline__ void load_stage(uint32_t sm, const __half* gA, const __half* gB,
                                           int it, int tid) {
    const int k0 = it * BK;
    #pragma unroll
    for (int r = 0; r < 8; r++) {
        int slot = tid + r * 128;          // 0..1023
        int row  = slot >> 3;              // 0..127
        int c    = slot & 7;               // 16B chunk within 128B row
        uint32_t sw = (uint32_t)(row * 128 + ((c ^ (row & 7)) << 4));
        cp16(sm + sw,         gA + (size_t)row * KC + k0 + c * 8);
        cp16(sm + 16384 + sw, gB + (size_t)row * KC + k0 + c * 8);
    }
}

__global__ __launch_bounds__(128, 2)
void versor_mma(float* __restrict__ out) {
    extern __shared__ char smem[];
    const uint32_t sbase = smem_u32(smem);
    const int tid  = threadIdx.x;
    const int wid  = tid >> 5;
    const int lane = tid & 31;
    const int wm   = wid & 1;
    const int wn   = wid >> 1;

    const int z     = blockIdx.x % 3;      // Gauss product; siblings adjacent in x
    const int ntile = blockIdx.x / 3;      // 8 n-tiles
    const int mtile = blockIdx.y;          // 64 m-tiles
    const int M0 = mtile * BM;
    const int N0 = ntile * BN;
    const int tileid = mtile * 8 + ntile;

    const __half* gA = g_A + (size_t)z * A_CHUNK + (size_t)M0 * KC;
    const __half* gB = g_B + (size_t)z * B_CHUNK + (size_t)N0 * KC;
    __half* gP = g_P + (size_t)z * P_CHUNK;

    const int lx  = lane & 7;
    const int akb = (lane >> 4) & 1;
    const int bkb = (lane >> 3) & 1;
    const uint32_t aRow = (uint32_t)((wm * 64 + lx + ((lane >> 3) & 1) * 8) * 128);
    const uint32_t bRow = 16384u + (uint32_t)((wn * 64 + lx + ((lane >> 4) & 1) * 8) * 128);

    float acc[4][8][4];
    #pragma unroll
    for (int mi = 0; mi < 4; mi++)
        #pragma unroll
        for (int nj = 0; nj < 8; nj++)
            #pragma unroll
            for (int q = 0; q < 4; q++) acc[mi][nj][q] = 0.0f;

    load_stage(sbase, gA, gB, 0, tid);
    asm volatile("cp.async.commit_group;" ::: "memory");
    load_stage(sbase + STAGE_BYTES, gA, gB, 1, tid);
    asm volatile("cp.async.commit_group;" ::: "memory");

    uint32_t a[2][4][4], b[2][4][4];   // double-buffered fragments

    #pragma unroll 1
    for (int it = 0; it < NIT; it++) {
        asm volatile("cp.async.wait_group 1;" ::: "memory");
        __syncthreads();

        const uint32_t sm = sbase + (uint32_t)(it % STAGES) * STAGE_BYTES;

        // fragments for ks0 + ks1 up front
        {
            const uint32_t cA0 = (uint32_t)((akb ^ lx) << 4);
            const uint32_t cB0 = (uint32_t)((bkb ^ lx) << 4);
            const uint32_t cA1 = (uint32_t)(((2 + akb) ^ lx) << 4);
            const uint32_t cB1 = (uint32_t)(((2 + bkb) ^ lx) << 4);
            #pragma unroll
            for (int mi = 0; mi < 4; mi++) {
                ldsm4(a[0][mi], sm + aRow + (uint32_t)(mi * 2048) + cA0);
                ldsm4(a[1][mi], sm + aRow + (uint32_t)(mi * 2048) + cA1);
            }
            #pragma unroll
            for (int nj2 = 0; nj2 < 4; nj2++) {
                ldsm4(b[0][nj2], sm + bRow + (uint32_t)(nj2 * 2048) + cB0);
                ldsm4(b[1][nj2], sm + bRow + (uint32_t)(nj2 * 2048) + cB1);
            }
        }
        // ks0 MMAs feed the tensor pipe while the cp.async burst issues below
        #pragma unroll
        for (int mi = 0; mi < 4; mi++)
            #pragma unroll
            for (int nj2 = 0; nj2 < 4; nj2++) {
                mma16(acc[mi][2 * nj2],     a[0][mi], b[0][nj2][0], b[0][nj2][1]);
                mma16(acc[mi][2 * nj2 + 1], a[0][mi], b[0][nj2][2], b[0][nj2][3]);
            }

        int nx = it + STAGES - 1;
        if (nx < NIT)
            load_stage(sbase + (uint32_t)(nx % STAGES) * STAGE_BYTES, gA, gB, nx, tid);
        asm volatile("cp.async.commit_group;" ::: "memory");

        #pragma unroll
        for (int ks = 1; ks < 4; ks++) {
            const int cur = ks & 1, nxt = cur ^ 1;
            if (ks < 3) {
                const uint32_t cA = (uint32_t)((((ks + 1) * 2 + akb) ^ lx) << 4);
                const uint32_t cB = (uint32_t)((((ks + 1) * 2 + bkb) ^ lx) << 4);
                #pragma unroll
                for (int mi = 0; mi < 4; mi++)
                    ldsm4(a[nxt][mi], sm + aRow + (uint32_t)(mi * 2048) + cA);
                #pragma unroll
                for (int nj2 = 0; nj2 < 4; nj2++)
                    ldsm4(b[nxt][nj2], sm + bRow + (uint32_t)(nj2 * 2048) + cB);
            }
            #pragma unroll
            for (int mi = 0; mi < 4; mi++)
                #pragma unroll
                for (int nj2 = 0; nj2 < 4; nj2++) {
                    mma16(acc[mi][2 * nj2],     a[cur][mi], b[cur][nj2][0], b[cur][nj2][1]);
                    mma16(acc[mi][2 * nj2 + 1], a[cur][mi], b[cur][nj2][2], b[cur][nj2][3]);
                }
        }
    }
    asm volatile("cp.async.wait_group 0;" ::: "memory");
    __syncthreads();

    const int qc   = lane & 3;
    const int rofs = lane >> 2;

    // ---- arrival-first protocol ----
    volatile unsigned* flag = reinterpret_cast<volatile unsigned*>(smem + FLAG_OFF);
    if (tid == 0) {
        unsigned r = atomicAdd(&g_cnt[tileid], 1u);
        unsigned last = (r == 2u);
        if (last) g_cnt[tileid] = 0u;    // self-reset for next graph replay
        flag[0] = last;
    }
    __syncthreads();

    if (flag[0] == 0u) {
        // not last: store my product tile as fp16, signal ready
        #pragma unroll
        for (int mi = 0; mi < 4; mi++) {
            const int row0 = M0 + wm * 64 + mi * 16 + rofs;
            #pragma unroll
            for (int nj = 0; nj < 8; nj++) {
                const int col = N0 + wn * 64 + nj * 8 + 2 * qc;
                *reinterpret_cast<__half2*>(gP + (size_t)row0 * NC + col) =
                    __floats2half2_rn(acc[mi][nj][0], acc[mi][nj][1]);
                *reinterpret_cast<__half2*>(gP + (size_t)(row0 + 8) * NC + col) =
                    __floats2half2_rn(acc[mi][nj][2], acc[mi][nj][3]);
            }
        }
        __threadfence();                 // publish P stores before ready increment
        __syncthreads();
        if (tid == 0) atomicAdd(&g_rdy[tileid], 1u);
        return;
    }

    // ================= last sibling: combine + blades + normalize =================
    float* S = reinterpret_cast<float*>(smem);   // overlays dead pipeline
    #pragma unroll
    for (int mi = 0; mi < 4; mi++) {
        const int rl = wm * 64 + mi * 16 + rofs;
        #pragma unroll
        for (int nj = 0; nj < 8; nj++) {
            const int cl = wn * 64 + nj * 8 + 2 * qc;
            *reinterpret_cast<float2*>(&S[rl * SROW + cl]) =
                make_float2(rt16(acc[mi][nj][0]), rt16(acc[mi][nj][1]));
            *reinterpret_cast<float2*>(&S[(rl + 8) * SROW + cl]) =
                make_float2(rt16(acc[mi][nj][2]), rt16(acc[mi][nj][3]));
        }
    }
    if (tid == 0) {
        while (atomicAdd(&g_rdy[tileid], 0u) < 2u) { }   // siblings' stores
        g_rdy[tileid] = 0u;              // self-reset for next graph replay
        __threadfence();                 // acquire
    }
    __syncthreads();

    const int za = (z + 1) % 3, zb = (z + 2) % 3;
    const __half* Pa = g_P + (size_t)za * P_CHUNK;
    const __half* Pb = g_P + (size_t)zb * P_CHUNK;

    #pragma unroll 1
    for (int e = 0; e < 8; e++) {
        const int cell = tid + e * 128;      // 0..1023
        const int t = cell >> 5;             // token within tile 0..31
        const int g = cell & 31;             // o-group 0..31
        float Mre[4][4], Mim[4][4];
        #pragma unroll
        for (int c = 0; c < 4; c++) {
            const size_t goff = (size_t)(M0 + 4 * t + c) * NC + N0 + 4 * g;
            float4 vo = *reinterpret_cast<const float4*>(&S[(4 * t + c) * SROW + 4 * g]);
            float4 va = ld4h(Pa + goff);
            float4 vb = ld4h(Pb + goff);
            float4 p1, p2, p3;
            if (z == 0)      { p1 = vo; p2 = va; p3 = vb; }
            else if (z == 1) { p1 = vb; p2 = vo; p3 = va; }
            else             { p1 = va; p2 = vb; p3 = vo; }
            Mre[0][c] = p1.x - p2.x; Mim[0][c] = p3.x - p1.x - p2.x;
            Mre[1][c] = p1.y - p2.y; Mim[1][c] = p3.y - p1.y - p2.y;
            Mre[2][c] = p1.z - p2.z; Mim[2][c] = p3.z - p1.z - p2.z;
            Mre[3][c] = p1.w - p2.w; Mim[3][c] = p3.w - p1.w - p2.w;
        }
        float v[32];
        blades(v, Mre, Mim, std::make_integer_sequence<int, 32>{});
        float ss = 1e-6f;
        #pragma unroll
        for (int k = 0; k < 32; k++) ss += v[k] * v[k];
        const float inv = rsqrtf(ss);

        const int n_global = (M0 >> 2) + t;
        const int o_global = (N0 >> 2) + g;
        float4* dst = reinterpret_cast<float4*>(out + ((size_t)n_global * 256 + o_global) * 32);
        #pragma unroll
        for (int q = 0; q < 8; q++)
            dst[q] = make_float4(v[4*q] * inv, v[4*q+1] * inv, v[4*q+2] * inv, v[4*q+3] * inv);
    }
}

// ================= host =================
extern "C" void kernel_launch(void* const* d_in, const int* in_sizes, int n_in,
                              void* d_out, int out_size) {
    const float* x = (const float*)d_in[0];   // [2048, 256, 32]
    const float* w = (const float*)d_in[1];   // [256, 256, 32]
    float* out = (float*)d_out;               // [2048, 256, 32]

    fwd_prep<<<WBLOCKS + (NTOK * IFEAT) / 256, 256>>>(x, w);

    cudaFuncSetAttribute(versor_mma, cudaFuncAttributeMaxDynamicSharedMemorySize, SMEM_TOTAL);
    dim3 grid(3 * (NC / BN), MDIM / BM);      // x: ntile*3 + z (siblings adjacent)
    versor_mma<<<grid, 128, SMEM_TOTAL>>>(out);
}